// round 12
// baseline (speedup 1.0000x reference)
#include <cuda_runtime.h>
#include <cuda_bf16.h>
#include <math.h>

// Problem constants (match reference)
#define NN   50000
#define EE   800000
#define INC  128
#define HID  256
#define NHEADS 4
#define OUTC 64

// -------- static device scratch (no allocations allowed) --------
__device__ float g_gbuf[(size_t)NN * HID];
__device__ float g_hbuf[(size_t)NN * HID];
__device__ float g_asrc[(size_t)NN * NHEADS];
__device__ float g_adst[(size_t)NN * NHEADS];
__device__ int   g_deg[NN];
__device__ int   g_rowptr[NN + 1];
__device__ int   g_cursor[NN];
__device__ int   g_adj[EE + NN];
__device__ int   g_bsum[64];
__device__ int   g_boff[64];

// ---------------- CSR construction ----------------
__global__ void zero_deg_kernel(int n) {
    int i = blockIdx.x * blockDim.x + threadIdx.x;
    if (i < n) g_deg[i] = 0;
}

__global__ void hist_kernel(const int* __restrict__ ei, int E, int n) {
    int e = blockIdx.x * blockDim.x + threadIdx.x;
    if (e < E) {
        int d = ei[E + e];
        if ((unsigned)d < (unsigned)n) atomicAdd(&g_deg[d], 1);
    }
}

__global__ void __launch_bounds__(1024) scan1_kernel(int n) {
    __shared__ int wsum[32];
    int t = threadIdx.x;
    int idx = blockIdx.x * 1024 + t;
    int v = (idx < n) ? (g_deg[idx] + 1) : 0;
    int incl = v;
#pragma unroll
    for (int o = 1; o < 32; o <<= 1) {
        int x = __shfl_up_sync(0xffffffffu, incl, o);
        if ((t & 31) >= o) incl += x;
    }
    if ((t & 31) == 31) wsum[t >> 5] = incl;
    __syncthreads();
    if (t < 32) {
        int w = wsum[t];
        int wi = w;
#pragma unroll
        for (int o = 1; o < 32; o <<= 1) {
            int x = __shfl_up_sync(0xffffffffu, wi, o);
            if (t >= o) wi += x;
        }
        wsum[t] = wi - w;
    }
    __syncthreads();
    int excl = incl - v + wsum[t >> 5];
    if (idx < n) g_rowptr[idx] = excl;
    if (t == 1023) g_bsum[blockIdx.x] = excl + v;
}

__global__ void __launch_bounds__(64) scan2_kernel(int nb, int n) {
    __shared__ int s[64];
    int t = threadIdx.x;
    int v = (t < nb) ? g_bsum[t] : 0;
    s[t] = v;
    __syncthreads();
    for (int o = 1; o < 64; o <<= 1) {
        int x = (t >= o) ? s[t - o] : 0;
        __syncthreads();
        s[t] += x;
        __syncthreads();
    }
    if (t < nb) g_boff[t] = s[t] - v;
    if (t == 63) g_rowptr[n] = s[63];
}

__global__ void __launch_bounds__(1024) scan3_kernel(int n) {
    int idx = blockIdx.x * 1024 + threadIdx.x;
    if (idx < n) g_rowptr[idx] += g_boff[blockIdx.x];
}

__global__ void selfloop_kernel(int n) {
    int i = blockIdx.x * blockDim.x + threadIdx.x;
    if (i < n) {
        int p = g_rowptr[i];
        g_adj[p] = i;
        g_cursor[i] = p + 1;
    }
}

__global__ void scatter_kernel(const int* __restrict__ ei, int E, int n) {
    int e = blockIdx.x * blockDim.x + threadIdx.x;
    if (e < E) {
        int s = ei[e];
        int d = ei[E + e];
        if ((unsigned)d < (unsigned)n && (unsigned)s < (unsigned)n) {
            int p = atomicAdd(&g_cursor[d], 1);
            g_adj[p] = s;
        }
    }
}

// ---------------- tf32 tensor-core GEMM, register-staged double buffer ----------------
__device__ __forceinline__ unsigned f2tf32(float f) {
    unsigned u;
    asm("cvt.rna.tf32.f32 %0, %1;" : "=r"(u) : "f"(f));
    return u;
}

__device__ __forceinline__ void mma_tf32(float* c, const unsigned* a, const unsigned* b) {
    asm volatile(
        "mma.sync.aligned.m16n8k8.row.col.f32.tf32.tf32.f32 "
        "{%0,%1,%2,%3},{%4,%5,%6,%7},{%8,%9},{%0,%1,%2,%3};"
        : "+f"(c[0]), "+f"(c[1]), "+f"(c[2]), "+f"(c[3])
        : "r"(a[0]), "r"(a[1]), "r"(a[2]), "r"(a[3]), "r"(b[0]), "r"(b[1]));
}

__global__ void __launch_bounds__(256) tf32gemm(const float* __restrict__ Aext,
                                                const float* __restrict__ B,
                                                int n, int K, int M, int use_hbuf) {
    const float* A = use_hbuf ? g_hbuf : Aext;
    __shared__ unsigned As[128 * 36];
    __shared__ unsigned Bs[32 * 136];

    const int tid = threadIdx.x;
    const int lane = tid & 31, wid = tid >> 5;
    const int wm = wid & 1, wn = wid >> 1;
    const int m0 = wm * 64, n0 = wn * 32;
    const int row0 = blockIdx.y * 128, col0 = blockIdx.x * 128;

    float acc[4][4][4];
#pragma unroll
    for (int i = 0; i < 4; i++)
#pragma unroll
        for (int j = 0; j < 4; j++)
#pragma unroll
            for (int q = 0; q < 4; q++) acc[i][j][q] = 0.f;

    const int ar = tid >> 3;
    const int ac4 = (tid & 7) * 4;
    const int bk = tid >> 5;
    const int bc4 = (tid & 31) * 4;
    const int colB = col0 + bc4;
    const bool colOk = colB < M;

    float4 pA[4], pB[4];
#pragma unroll
    for (int j = 0; j < 4; j++) {
        int grow = row0 + ar + 32 * j;
        pA[j] = (grow < n) ? *(const float4*)&A[(size_t)grow * K + ac4]
                           : make_float4(0.f, 0.f, 0.f, 0.f);
        pB[j] = colOk ? *(const float4*)&B[(size_t)(bk + 8 * j) * M + colB]
                      : make_float4(0.f, 0.f, 0.f, 0.f);
    }

    for (int k0 = 0; k0 < K; k0 += 32) {
#pragma unroll
        for (int j = 0; j < 4; j++) {
            *(uint4*)&As[(ar + 32 * j) * 36 + ac4] =
                make_uint4(f2tf32(pA[j].x), f2tf32(pA[j].y), f2tf32(pA[j].z), f2tf32(pA[j].w));
            *(uint4*)&Bs[(bk + 8 * j) * 136 + bc4] =
                make_uint4(f2tf32(pB[j].x), f2tf32(pB[j].y), f2tf32(pB[j].z), f2tf32(pB[j].w));
        }
        __syncthreads();

        if (k0 + 32 < K) {
            int kn = k0 + 32;
#pragma unroll
            for (int j = 0; j < 4; j++) {
                int grow = row0 + ar + 32 * j;
                pA[j] = (grow < n) ? *(const float4*)&A[(size_t)grow * K + kn + ac4]
                                   : make_float4(0.f, 0.f, 0.f, 0.f);
                pB[j] = colOk ? *(const float4*)&B[(size_t)(kn + bk + 8 * j) * M + colB]
                              : make_float4(0.f, 0.f, 0.f, 0.f);
            }
        }

#pragma unroll
        for (int k8 = 0; k8 < 32; k8 += 8) {
            unsigned a[4][4], b[4][2];
#pragma unroll
            for (int mt = 0; mt < 4; mt++) {
                int r = m0 + mt * 16 + (lane >> 2);
                int c = k8 + (lane & 3);
                a[mt][0] = As[r * 36 + c];
                a[mt][1] = As[(r + 8) * 36 + c];
                a[mt][2] = As[r * 36 + c + 4];
                a[mt][3] = As[(r + 8) * 36 + c + 4];
            }
#pragma unroll
            for (int nt = 0; nt < 4; nt++) {
                int col = n0 + nt * 8 + (lane >> 2);
                b[nt][0] = Bs[(k8 + (lane & 3)) * 136 + col];
                b[nt][1] = Bs[(k8 + (lane & 3) + 4) * 136 + col];
            }
#pragma unroll
            for (int mt = 0; mt < 4; mt++)
#pragma unroll
                for (int nt = 0; nt < 4; nt++) mma_tf32(acc[mt][nt], a[mt], b[nt]);
        }
        __syncthreads();
    }

#pragma unroll
    for (int mt = 0; mt < 4; mt++) {
#pragma unroll
        for (int nt = 0; nt < 4; nt++) {
            int row = row0 + m0 + mt * 16 + (lane >> 2);
            int col = col0 + n0 + nt * 8 + 2 * (lane & 3);
            if (col < M) {
                if (row < n)
                    *(float2*)&g_gbuf[(size_t)row * M + col] =
                        make_float2(acc[mt][nt][0], acc[mt][nt][1]);
                if (row + 8 < n)
                    *(float2*)&g_gbuf[(size_t)(row + 8) * M + col] =
                        make_float2(acc[mt][nt][2], acc[mt][nt][3]);
            }
        }
    }
}

// ---------------- attention score dots ----------------
template <int H, int C>
__global__ void att_kernel(const float* __restrict__ as, const float* __restrict__ ad, int n) {
    int node = blockIdx.x;
    if (node >= n) return;
    int w = threadIdx.x >> 5, lane = threadIdx.x & 31;
    float vs = 0.f, vd = 0.f;
    const float* row = g_gbuf + (size_t)node * (H * C) + w * C;
#pragma unroll
    for (int c = lane; c < C; c += 32) {
        float x = row[c];
        vs += x * as[w * C + c];
        vd += x * ad[w * C + c];
    }
#pragma unroll
    for (int o = 16; o > 0; o >>= 1) {
        vs += __shfl_down_sync(0xffffffffu, vs, o);
        vd += __shfl_down_sync(0xffffffffu, vd, o);
    }
    if (lane == 0) {
        g_asrc[node * H + w] = vs;
        g_adst[node * H + w] = vd;
    }
}

// ---------------- fused softmax + warp-per-node gather aggregation ----------------
// One warp per node. Per edge: broadcast adj load, broadcast asrc float4 load,
// uniform leakyrelu+exp (redundant per lane, free under L2 latency), lane picks
// its head's weight and accumulates its head's denominator in a register.
// Normalization by 1/denom at the end. No g_w, no g_denom, no atomics.
template <int CH, int H, bool DO_BN>
__global__ void __launch_bounds__(256) agg7_kernel(int n,
                                                   const float* __restrict__ bias,
                                                   const float* __restrict__ bn_g,
                                                   const float* __restrict__ bn_b,
                                                   const float* __restrict__ bn_m,
                                                   const float* __restrict__ bn_v,
                                                   float* __restrict__ out_ext) {
    constexpr int VEC = CH / 32;        // channels per lane (8 or 2)
    constexpr int C = CH / H;

    float* out = out_ext ? out_ext : g_hbuf;
    const int warp = threadIdx.x >> 5;
    const int lane = threadIdx.x & 31;
    const int node = blockIdx.x * 8 + warp;
    if (node >= n) return;
    const int c0 = lane * VEC;
    const int head = c0 / C;

    const int beg = g_rowptr[node];
    const int end = g_rowptr[node + 1];

    // destination attention terms (broadcast)
    float adst0, adst1, adst2, adst3;
    if constexpr (H == 4) {
        float4 bdst = *(const float4*)&g_adst[node * 4];
        adst0 = bdst.x; adst1 = bdst.y; adst2 = bdst.z; adst3 = bdst.w;
    } else {
        adst0 = __ldg(&g_adst[node]);
    }

    float acc[VEC];
#pragma unroll
    for (int v = 0; v < VEC; v++) acc[v] = 0.f;
    float denom = 0.f;

#pragma unroll 4
    for (int i = beg; i < end; i++) {
        const int s = __ldg(&g_adj[i]);                      // warp-broadcast
        float w;
        if constexpr (H == 4) {
            float4 a = *(const float4*)&g_asrc[s * 4];       // broadcast 16B
            float e0 = a.x + adst0, e1 = a.y + adst1;
            float e2 = a.z + adst2, e3 = a.w + adst3;
            e0 = (e0 > 0.f) ? e0 : 0.2f * e0;
            e1 = (e1 > 0.f) ? e1 : 0.2f * e1;
            e2 = (e2 > 0.f) ? e2 : 0.2f * e2;
            e3 = (e3 > 0.f) ? e3 : 0.2f * e3;
            float w0 = __expf(e0), w1 = __expf(e1), w2 = __expf(e2), w3 = __expf(e3);
            w = (head == 0) ? w0 : (head == 1) ? w1 : (head == 2) ? w2 : w3;
        } else {
            float e = __ldg(&g_asrc[s]) + adst0;
            e = (e > 0.f) ? e : 0.2f * e;
            w = __expf(e);
        }
        denom += w;
        const float* row = &g_gbuf[(size_t)s * CH + c0];
        if constexpr (VEC == 8) {
            float4 v0 = *(const float4*)row;
            float4 v1 = *(const float4*)(row + 4);
            acc[0] += w * v0.x; acc[1] += w * v0.y;
            acc[2] += w * v0.z; acc[3] += w * v0.w;
            acc[4] += w * v1.x; acc[5] += w * v1.y;
            acc[6] += w * v1.z; acc[7] += w * v1.w;
        } else {
            float2 v0 = *(const float2*)row;
            acc[0] += w * v0.x; acc[1] += w * v0.y;
        }
    }

    const float inv = 1.f / (denom + 1e-16f);
    float o[VEC];
#pragma unroll
    for (int v = 0; v < VEC; v++) o[v] = acc[v] * inv + __ldg(&bias[c0 + v]);
    if (DO_BN) {
#pragma unroll
        for (int v = 0; v < VEC; v++) {
            float val = (o[v] - __ldg(&bn_m[c0 + v])) * rsqrtf(__ldg(&bn_v[c0 + v]) + 1e-5f)
                        * __ldg(&bn_g[c0 + v]) + __ldg(&bn_b[c0 + v]);
            o[v] = (val > 0.f) ? val : expm1f(val);
        }
    }
    if constexpr (VEC == 8) {
        *(float4*)&out[(size_t)node * CH + c0] = make_float4(o[0], o[1], o[2], o[3]);
        *(float4*)&out[(size_t)node * CH + c0 + 4] = make_float4(o[4], o[5], o[6], o[7]);
    } else {
        *(float2*)&out[(size_t)node * CH + c0] = make_float2(o[0], o[1]);
    }
}

// ---------------- launch ----------------
extern "C" void kernel_launch(void* const* d_in, const int* in_sizes, int n_in,
                              void* d_out, int out_size) {
    const float* x   = (const float*)d_in[0];
    const int*   ei  = (const int*)d_in[1];     // int32 (JAX default x64-disabled)
    const float* W0  = (const float*)d_in[2];
    const float* as0 = (const float*)d_in[3];
    const float* ad0 = (const float*)d_in[4];
    const float* b0  = (const float*)d_in[5];
    const float* bn0g = (const float*)d_in[6];
    const float* bn0b = (const float*)d_in[7];
    const float* bn0m = (const float*)d_in[8];
    const float* bn0v = (const float*)d_in[9];
    const float* W1  = (const float*)d_in[10];
    const float* as1 = (const float*)d_in[11];
    const float* ad1 = (const float*)d_in[12];
    const float* b1  = (const float*)d_in[13];
    const float* bn1g = (const float*)d_in[14];
    const float* bn1b = (const float*)d_in[15];
    const float* bn1m = (const float*)d_in[16];
    const float* bn1v = (const float*)d_in[17];
    const float* W2  = (const float*)d_in[18];
    const float* as2 = (const float*)d_in[19];
    const float* ad2 = (const float*)d_in[20];
    const float* b2  = (const float*)d_in[21];

    int n = in_sizes[0] / INC;       // 50000
    int E = in_sizes[1] / 2;         // 800000

    // ---- CSR build ----
    zero_deg_kernel<<<(n + 255) / 256, 256>>>(n);
    hist_kernel<<<(E + 255) / 256, 256>>>(ei, E, n);
    int nb = (n + 1023) / 1024;
    scan1_kernel<<<nb, 1024>>>(n);
    scan2_kernel<<<1, 64>>>(nb, n);
    scan3_kernel<<<nb, 1024>>>(n);
    selfloop_kernel<<<(n + 255) / 256, 256>>>(n);
    scatter_kernel<<<(E + 255) / 256, 256>>>(ei, E, n);

    dim3 gA((HID + 127) / 128, (n + 127) / 128);
    dim3 gC((OUTC + 127) / 128, (n + 127) / 128);
    int gN = (n + 7) / 8;

    // ---- layer 0: 128 -> 256, 4 heads, concat, BN+ELU ----
    tf32gemm<<<gA, 256>>>(x, W0, n, INC, HID, 0);
    att_kernel<NHEADS, HID / NHEADS><<<n, 32 * NHEADS>>>(as0, ad0, n);
    agg7_kernel<HID, NHEADS, true><<<gN, 256>>>(n, b0, bn0g, bn0b, bn0m, bn0v, nullptr);

    // ---- layer 1: 256 -> 256, 4 heads, concat, BN+ELU ----
    tf32gemm<<<gA, 256>>>(nullptr, W1, n, HID, HID, 1);
    att_kernel<NHEADS, HID / NHEADS><<<n, 32 * NHEADS>>>(as1, ad1, n);
    agg7_kernel<HID, NHEADS, true><<<gN, 256>>>(n, b1, bn1g, bn1b, bn1m, bn1v, nullptr);

    // ---- layer 2: 256 -> 64, 1 head, mean(=identity), bias only ----
    tf32gemm<<<gC, 256>>>(nullptr, W2, n, HID, OUTC, 1);
    att_kernel<1, OUTC><<<n, 32>>>(as2, ad2, n);
    agg7_kernel<OUTC, 1, false><<<gN, 256>>>(n, b2, b2, b2, b2, b2, (float*)d_out);
}

// round 13
// speedup vs baseline: 1.0461x; 1.0461x over previous
#include <cuda_runtime.h>
#include <cuda_bf16.h>
#include <math.h>

// Problem constants (match reference)
#define NN   50000
#define EE   800000
#define INC  128
#define HID  256
#define NHEADS 4
#define OUTC 64

// -------- static device scratch (no allocations allowed) --------
__device__ float g_gbuf[(size_t)NN * HID];
__device__ float g_hbuf[(size_t)NN * HID];
__device__ float g_asrc[(size_t)NN * NHEADS];
__device__ float g_adst[(size_t)NN * NHEADS];
__device__ float g_denom[(size_t)NN * NHEADS];
__device__ float g_w[(size_t)(EE + NN) * NHEADS];
__device__ int   g_deg[NN];
__device__ int   g_rowptr[NN + 1];
__device__ int   g_cursor[NN];
__device__ int   g_adj[EE + NN];
__device__ int   g_edst[EE + NN];
__device__ int   g_bsum[64];
__device__ int   g_boff[64];

// ---------------- CSR construction ----------------
__global__ void zero_deg_kernel(int n) {
    int i = blockIdx.x * blockDim.x + threadIdx.x;
    if (i < n) g_deg[i] = 0;
}

__global__ void hist_kernel(const int* __restrict__ ei, int E, int n) {
    int e = blockIdx.x * blockDim.x + threadIdx.x;
    if (e < E) {
        int d = ei[E + e];
        if ((unsigned)d < (unsigned)n) atomicAdd(&g_deg[d], 1);
    }
}

__global__ void __launch_bounds__(1024) scan1_kernel(int n) {
    __shared__ int wsum[32];
    int t = threadIdx.x;
    int idx = blockIdx.x * 1024 + t;
    int v = (idx < n) ? (g_deg[idx] + 1) : 0;
    int incl = v;
#pragma unroll
    for (int o = 1; o < 32; o <<= 1) {
        int x = __shfl_up_sync(0xffffffffu, incl, o);
        if ((t & 31) >= o) incl += x;
    }
    if ((t & 31) == 31) wsum[t >> 5] = incl;
    __syncthreads();
    if (t < 32) {
        int w = wsum[t];
        int wi = w;
#pragma unroll
        for (int o = 1; o < 32; o <<= 1) {
            int x = __shfl_up_sync(0xffffffffu, wi, o);
            if (t >= o) wi += x;
        }
        wsum[t] = wi - w;
    }
    __syncthreads();
    int excl = incl - v + wsum[t >> 5];
    if (idx < n) g_rowptr[idx] = excl;
    if (t == 1023) g_bsum[blockIdx.x] = excl + v;
}

__global__ void __launch_bounds__(64) scan2_kernel(int nb, int n) {
    __shared__ int s[64];
    int t = threadIdx.x;
    int v = (t < nb) ? g_bsum[t] : 0;
    s[t] = v;
    __syncthreads();
    for (int o = 1; o < 64; o <<= 1) {
        int x = (t >= o) ? s[t - o] : 0;
        __syncthreads();
        s[t] += x;
        __syncthreads();
    }
    if (t < nb) g_boff[t] = s[t] - v;
    if (t == 63) g_rowptr[n] = s[63];
}

__global__ void __launch_bounds__(1024) scan3_kernel(int n) {
    int idx = blockIdx.x * 1024 + threadIdx.x;
    if (idx < n) g_rowptr[idx] += g_boff[blockIdx.x];
}

__global__ void selfloop_kernel(int n) {
    int i = blockIdx.x * blockDim.x + threadIdx.x;
    if (i < n) {
        int p = g_rowptr[i];
        g_adj[p] = i;
        g_edst[p] = i;
        g_cursor[i] = p + 1;
    }
}

__global__ void scatter_kernel(const int* __restrict__ ei, int E, int n) {
    int e = blockIdx.x * blockDim.x + threadIdx.x;
    if (e < E) {
        int s = ei[e];
        int d = ei[E + e];
        if ((unsigned)d < (unsigned)n && (unsigned)s < (unsigned)n) {
            int p = atomicAdd(&g_cursor[d], 1);
            g_adj[p] = s;
            g_edst[p] = d;
        }
    }
}

// ---------------- tf32 tensor-core GEMM, register-staged double buffer ----------------
__device__ __forceinline__ unsigned f2tf32(float f) {
    unsigned u;
    asm("cvt.rna.tf32.f32 %0, %1;" : "=r"(u) : "f"(f));
    return u;
}

__device__ __forceinline__ void mma_tf32(float* c, const unsigned* a, const unsigned* b) {
    asm volatile(
        "mma.sync.aligned.m16n8k8.row.col.f32.tf32.tf32.f32 "
        "{%0,%1,%2,%3},{%4,%5,%6,%7},{%8,%9},{%0,%1,%2,%3};"
        : "+f"(c[0]), "+f"(c[1]), "+f"(c[2]), "+f"(c[3])
        : "r"(a[0]), "r"(a[1]), "r"(a[2]), "r"(a[3]), "r"(b[0]), "r"(b[1]));
}

__global__ void __launch_bounds__(256) tf32gemm(const float* __restrict__ Aext,
                                                const float* __restrict__ B,
                                                int n, int K, int M, int use_hbuf) {
    const float* A = use_hbuf ? g_hbuf : Aext;
    __shared__ unsigned As[128 * 36];
    __shared__ unsigned Bs[32 * 136];

    const int tid = threadIdx.x;
    const int lane = tid & 31, wid = tid >> 5;
    const int wm = wid & 1, wn = wid >> 1;
    const int m0 = wm * 64, n0 = wn * 32;
    const int row0 = blockIdx.y * 128, col0 = blockIdx.x * 128;

    float acc[4][4][4];
#pragma unroll
    for (int i = 0; i < 4; i++)
#pragma unroll
        for (int j = 0; j < 4; j++)
#pragma unroll
            for (int q = 0; q < 4; q++) acc[i][j][q] = 0.f;

    const int ar = tid >> 3;
    const int ac4 = (tid & 7) * 4;
    const int bk = tid >> 5;
    const int bc4 = (tid & 31) * 4;
    const int colB = col0 + bc4;
    const bool colOk = colB < M;

    float4 pA[4], pB[4];
#pragma unroll
    for (int j = 0; j < 4; j++) {
        int grow = row0 + ar + 32 * j;
        pA[j] = (grow < n) ? *(const float4*)&A[(size_t)grow * K + ac4]
                           : make_float4(0.f, 0.f, 0.f, 0.f);
        pB[j] = colOk ? *(const float4*)&B[(size_t)(bk + 8 * j) * M + colB]
                      : make_float4(0.f, 0.f, 0.f, 0.f);
    }

    for (int k0 = 0; k0 < K; k0 += 32) {
#pragma unroll
        for (int j = 0; j < 4; j++) {
            *(uint4*)&As[(ar + 32 * j) * 36 + ac4] =
                make_uint4(f2tf32(pA[j].x), f2tf32(pA[j].y), f2tf32(pA[j].z), f2tf32(pA[j].w));
            *(uint4*)&Bs[(bk + 8 * j) * 136 + bc4] =
                make_uint4(f2tf32(pB[j].x), f2tf32(pB[j].y), f2tf32(pB[j].z), f2tf32(pB[j].w));
        }
        __syncthreads();

        if (k0 + 32 < K) {
            int kn = k0 + 32;
#pragma unroll
            for (int j = 0; j < 4; j++) {
                int grow = row0 + ar + 32 * j;
                pA[j] = (grow < n) ? *(const float4*)&A[(size_t)grow * K + kn + ac4]
                                   : make_float4(0.f, 0.f, 0.f, 0.f);
                pB[j] = colOk ? *(const float4*)&B[(size_t)(kn + bk + 8 * j) * M + colB]
                              : make_float4(0.f, 0.f, 0.f, 0.f);
            }
        }

#pragma unroll
        for (int k8 = 0; k8 < 32; k8 += 8) {
            unsigned a[4][4], b[4][2];
#pragma unroll
            for (int mt = 0; mt < 4; mt++) {
                int r = m0 + mt * 16 + (lane >> 2);
                int c = k8 + (lane & 3);
                a[mt][0] = As[r * 36 + c];
                a[mt][1] = As[(r + 8) * 36 + c];
                a[mt][2] = As[r * 36 + c + 4];
                a[mt][3] = As[(r + 8) * 36 + c + 4];
            }
#pragma unroll
            for (int nt = 0; nt < 4; nt++) {
                int col = n0 + nt * 8 + (lane >> 2);
                b[nt][0] = Bs[(k8 + (lane & 3)) * 136 + col];
                b[nt][1] = Bs[(k8 + (lane & 3) + 4) * 136 + col];
            }
#pragma unroll
            for (int mt = 0; mt < 4; mt++)
#pragma unroll
                for (int nt = 0; nt < 4; nt++) mma_tf32(acc[mt][nt], a[mt], b[nt]);
        }
        __syncthreads();
    }

#pragma unroll
    for (int mt = 0; mt < 4; mt++) {
#pragma unroll
        for (int nt = 0; nt < 4; nt++) {
            int row = row0 + m0 + mt * 16 + (lane >> 2);
            int col = col0 + n0 + nt * 8 + 2 * (lane & 3);
            if (col < M) {
                if (row < n)
                    *(float2*)&g_gbuf[(size_t)row * M + col] =
                        make_float2(acc[mt][nt][0], acc[mt][nt][1]);
                if (row + 8 < n)
                    *(float2*)&g_gbuf[(size_t)(row + 8) * M + col] =
                        make_float2(acc[mt][nt][2], acc[mt][nt][3]);
            }
        }
    }
}

// ---------------- attention score dots (also zeroes denominators) ----------------
template <int H, int C>
__global__ void att_kernel(const float* __restrict__ as, const float* __restrict__ ad, int n) {
    int node = blockIdx.x;
    if (node >= n) return;
    int w = threadIdx.x >> 5, lane = threadIdx.x & 31;
    float vs = 0.f, vd = 0.f;
    const float* row = g_gbuf + (size_t)node * (H * C) + w * C;
#pragma unroll
    for (int c = lane; c < C; c += 32) {
        float x = row[c];
        vs += x * as[w * C + c];
        vd += x * ad[w * C + c];
    }
#pragma unroll
    for (int o = 16; o > 0; o >>= 1) {
        vs += __shfl_down_sync(0xffffffffu, vs, o);
        vd += __shfl_down_sync(0xffffffffu, vd, o);
    }
    if (lane == 0) {
        g_asrc[node * H + w] = vs;
        g_adst[node * H + w] = vd;
        g_denom[node * H + w] = 0.f;
    }
}

// ---------------- per-edge softmax weights (max-free; scores are O(1)) ----------------
template <int H>
__global__ void edgew_kernel(int Et) {
    int i = blockIdx.x * blockDim.x + threadIdx.x;
    if (i >= Et) return;
    int s = g_adj[i];
    int d = g_edst[i];
    if constexpr (H == 4) {
        float4 a = *(const float4*)&g_asrc[s * 4];
        float4 b = *(const float4*)&g_adst[d * 4];
        float e0 = a.x + b.x, e1 = a.y + b.y, e2 = a.z + b.z, e3 = a.w + b.w;
        e0 = (e0 > 0.f) ? e0 : 0.2f * e0;
        e1 = (e1 > 0.f) ? e1 : 0.2f * e1;
        e2 = (e2 > 0.f) ? e2 : 0.2f * e2;
        e3 = (e3 > 0.f) ? e3 : 0.2f * e3;
        float w0 = __expf(e0), w1 = __expf(e1), w2 = __expf(e2), w3 = __expf(e3);
        *(float4*)&g_w[(size_t)i * 4] = make_float4(w0, w1, w2, w3);
        atomicAdd(&g_denom[d * 4 + 0], w0);
        atomicAdd(&g_denom[d * 4 + 1], w1);
        atomicAdd(&g_denom[d * 4 + 2], w2);
        atomicAdd(&g_denom[d * 4 + 3], w3);
    } else {
        float e = g_asrc[s] + g_adst[d];
        e = (e > 0.f) ? e : 0.2f * e;
        float w = __expf(e);
        g_w[i] = w;
        atomicAdd(&g_denom[d], w);
    }
}

// ---------------- warp-per-node gather aggregation ----------------
template <int CH, int H, bool DO_BN>
__global__ void __launch_bounds__(256) agg6_kernel(int n,
                                                   const float* __restrict__ bias,
                                                   const float* __restrict__ bn_g,
                                                   const float* __restrict__ bn_b,
                                                   const float* __restrict__ bn_m,
                                                   const float* __restrict__ bn_v,
                                                   float* __restrict__ out_ext) {
    constexpr int VEC = CH / 32;        // channels per lane (8 or 2)
    constexpr int C = CH / H;

    float* out = out_ext ? out_ext : g_hbuf;
    const int warp = threadIdx.x >> 5;
    const int lane = threadIdx.x & 31;
    const int node = blockIdx.x * 8 + warp;
    if (node >= n) return;
    const int c0 = lane * VEC;
    const int head = c0 / C;

    const int beg = g_rowptr[node];
    const int end = g_rowptr[node + 1];

    float acc[VEC];
#pragma unroll
    for (int v = 0; v < VEC; v++) acc[v] = 0.f;

#pragma unroll 4
    for (int i = beg; i < end; i++) {
        const int s = __ldg(&g_adj[i]);                      // warp-broadcast
        const float w = __ldg(&g_w[(size_t)i * H + head]);   // 1 line per warp
        const float* row = &g_gbuf[(size_t)s * CH + c0];
        if constexpr (VEC == 8) {
            float4 v0 = *(const float4*)row;
            float4 v1 = *(const float4*)(row + 4);
            acc[0] += w * v0.x; acc[1] += w * v0.y;
            acc[2] += w * v0.z; acc[3] += w * v0.w;
            acc[4] += w * v1.x; acc[5] += w * v1.y;
            acc[6] += w * v1.z; acc[7] += w * v1.w;
        } else {
            float2 v0 = *(const float2*)row;
            acc[0] += w * v0.x; acc[1] += w * v0.y;
        }
    }

    const float inv = 1.f / (__ldg(&g_denom[node * H + head]) + 1e-16f);
    float o[VEC];
#pragma unroll
    for (int v = 0; v < VEC; v++) o[v] = acc[v] * inv + __ldg(&bias[c0 + v]);
    if (DO_BN) {
#pragma unroll
        for (int v = 0; v < VEC; v++) {
            float val = (o[v] - __ldg(&bn_m[c0 + v])) * rsqrtf(__ldg(&bn_v[c0 + v]) + 1e-5f)
                        * __ldg(&bn_g[c0 + v]) + __ldg(&bn_b[c0 + v]);
            o[v] = (val > 0.f) ? val : expm1f(val);
        }
    }
    if constexpr (VEC == 8) {
        *(float4*)&out[(size_t)node * CH + c0] = make_float4(o[0], o[1], o[2], o[3]);
        *(float4*)&out[(size_t)node * CH + c0 + 4] = make_float4(o[4], o[5], o[6], o[7]);
    } else {
        *(float2*)&out[(size_t)node * CH + c0] = make_float2(o[0], o[1]);
    }
}

// ---------------- launch ----------------
extern "C" void kernel_launch(void* const* d_in, const int* in_sizes, int n_in,
                              void* d_out, int out_size) {
    const float* x   = (const float*)d_in[0];
    const int*   ei  = (const int*)d_in[1];     // int32 (JAX default x64-disabled)
    const float* W0  = (const float*)d_in[2];
    const float* as0 = (const float*)d_in[3];
    const float* ad0 = (const float*)d_in[4];
    const float* b0  = (const float*)d_in[5];
    const float* bn0g = (const float*)d_in[6];
    const float* bn0b = (const float*)d_in[7];
    const float* bn0m = (const float*)d_in[8];
    const float* bn0v = (const float*)d_in[9];
    const float* W1  = (const float*)d_in[10];
    const float* as1 = (const float*)d_in[11];
    const float* ad1 = (const float*)d_in[12];
    const float* b1  = (const float*)d_in[13];
    const float* bn1g = (const float*)d_in[14];
    const float* bn1b = (const float*)d_in[15];
    const float* bn1m = (const float*)d_in[16];
    const float* bn1v = (const float*)d_in[17];
    const float* W2  = (const float*)d_in[18];
    const float* as2 = (const float*)d_in[19];
    const float* ad2 = (const float*)d_in[20];
    const float* b2  = (const float*)d_in[21];

    int n = in_sizes[0] / INC;       // 50000
    int E = in_sizes[1] / 2;         // 800000
    int Et = E + n;

    // side stream + events for forked capture (created once, host-side only)
    static cudaStream_t s_side = nullptr;
    static cudaEvent_t s_fork = nullptr, s_join = nullptr;
    if (s_side == nullptr) {
        cudaStreamCreateWithFlags(&s_side, cudaStreamNonBlocking);
        cudaEventCreateWithFlags(&s_fork, cudaEventDisableTiming);
        cudaEventCreateWithFlags(&s_join, cudaEventDisableTiming);
    }

    dim3 gA((HID + 127) / 128, (n + 127) / 128);
    dim3 gC((OUTC + 127) / 128, (n + 127) / 128);
    int gE = (Et + 255) / 256;
    int gN = (n + 7) / 8;
    int nb = (n + 1023) / 1024;

    // ---- fork: CSR build on side stream, concurrent with layer-0 GEMM+att ----
    cudaEventRecord(s_fork, 0);
    cudaStreamWaitEvent(s_side, s_fork, 0);
    zero_deg_kernel<<<(n + 255) / 256, 256, 0, s_side>>>(n);
    hist_kernel<<<(E + 255) / 256, 256, 0, s_side>>>(ei, E, n);
    scan1_kernel<<<nb, 1024, 0, s_side>>>(n);
    scan2_kernel<<<1, 64, 0, s_side>>>(nb, n);
    scan3_kernel<<<nb, 1024, 0, s_side>>>(n);
    selfloop_kernel<<<(n + 255) / 256, 256, 0, s_side>>>(n);
    scatter_kernel<<<(E + 255) / 256, 256, 0, s_side>>>(ei, E, n);
    cudaEventRecord(s_join, s_side);

    // ---- layer 0 GEMM + att dots (independent of CSR) ----
    tf32gemm<<<gA, 256>>>(x, W0, n, INC, HID, 0);
    att_kernel<NHEADS, HID / NHEADS><<<n, 32 * NHEADS>>>(as0, ad0, n);

    cudaStreamWaitEvent(0, s_join, 0);   // join before first edge pass

    // ---- layer 0: edge softmax + aggregation ----
    edgew_kernel<NHEADS><<<gE, 256>>>(Et);
    agg6_kernel<HID, NHEADS, true><<<gN, 256>>>(n, b0, bn0g, bn0b, bn0m, bn0v, nullptr);

    // ---- layer 1: 256 -> 256, 4 heads, concat, BN+ELU ----
    tf32gemm<<<gA, 256>>>(nullptr, W1, n, HID, HID, 1);
    att_kernel<NHEADS, HID / NHEADS><<<n, 32 * NHEADS>>>(as1, ad1, n);
    edgew_kernel<NHEADS><<<gE, 256>>>(Et);
    agg6_kernel<HID, NHEADS, true><<<gN, 256>>>(n, b1, bn1g, bn1b, bn1m, bn1v, nullptr);

    // ---- layer 2: 256 -> 64, 1 head, mean(=identity), bias only ----
    tf32gemm<<<gC, 256>>>(nullptr, W2, n, HID, OUTC, 1);
    att_kernel<1, OUTC><<<n, 32>>>(as2, ad2, n);
    edgew_kernel<1><<<gE, 256>>>(Et);
    agg6_kernel<OUTC, 1, false><<<gN, 256>>>(n, b2, b2, b2, b2, b2, (float*)d_out);
}

// round 16
// speedup vs baseline: 1.1727x; 1.1210x over previous
#include <cuda_runtime.h>
#include <cuda_bf16.h>
#include <math.h>

// Problem constants (match reference)
#define NN   50000
#define EE   800000
#define INC  128
#define HID  256
#define NHEADS 4
#define OUTC 64

// -------- static device scratch (no allocations allowed) --------
__device__ float g_gbuf[(size_t)NN * HID];
__device__ float g_hbuf[(size_t)NN * HID];
__device__ float g_asrc[(size_t)NN * NHEADS];
__device__ float g_adst[(size_t)NN * NHEADS];
__device__ int   g_deg[NN];
__device__ int   g_rowptr[NN + 1];
__device__ int   g_cursor[NN];
__device__ int   g_adj[EE + NN];
__device__ int   g_bsum[64];
__device__ int   g_boff[64];

// ---------------- CSR construction ----------------
__global__ void zero_deg_kernel(int n) {
    int i = blockIdx.x * blockDim.x + threadIdx.x;
    if (i < n) g_deg[i] = 0;
}

__global__ void hist_kernel(const int* __restrict__ ei, int E, int n) {
    int e = blockIdx.x * blockDim.x + threadIdx.x;
    if (e < E) {
        int d = ei[E + e];
        if ((unsigned)d < (unsigned)n) atomicAdd(&g_deg[d], 1);
    }
}

__global__ void __launch_bounds__(1024) scan1_kernel(int n) {
    __shared__ int wsum[32];
    int t = threadIdx.x;
    int idx = blockIdx.x * 1024 + t;
    int v = (idx < n) ? (g_deg[idx] + 1) : 0;
    int incl = v;
#pragma unroll
    for (int o = 1; o < 32; o <<= 1) {
        int x = __shfl_up_sync(0xffffffffu, incl, o);
        if ((t & 31) >= o) incl += x;
    }
    if ((t & 31) == 31) wsum[t >> 5] = incl;
    __syncthreads();
    if (t < 32) {
        int w = wsum[t];
        int wi = w;
#pragma unroll
        for (int o = 1; o < 32; o <<= 1) {
            int x = __shfl_up_sync(0xffffffffu, wi, o);
            if (t >= o) wi += x;
        }
        wsum[t] = wi - w;
    }
    __syncthreads();
    int excl = incl - v + wsum[t >> 5];
    if (idx < n) g_rowptr[idx] = excl;
    if (t == 1023) g_bsum[blockIdx.x] = excl + v;
}

__global__ void __launch_bounds__(64) scan2_kernel(int nb, int n) {
    __shared__ int s[64];
    int t = threadIdx.x;
    int v = (t < nb) ? g_bsum[t] : 0;
    s[t] = v;
    __syncthreads();
    for (int o = 1; o < 64; o <<= 1) {
        int x = (t >= o) ? s[t - o] : 0;
        __syncthreads();
        s[t] += x;
        __syncthreads();
    }
    if (t < nb) g_boff[t] = s[t] - v;
    if (t == 63) g_rowptr[n] = s[63];
}

__global__ void __launch_bounds__(1024) scan3_kernel(int n) {
    int idx = blockIdx.x * 1024 + threadIdx.x;
    if (idx < n) g_rowptr[idx] += g_boff[blockIdx.x];
}

__global__ void selfloop_kernel(int n) {
    int i = blockIdx.x * blockDim.x + threadIdx.x;
    if (i < n) {
        int p = g_rowptr[i];
        g_adj[p] = i;
        g_cursor[i] = p + 1;
    }
}

__global__ void scatter_kernel(const int* __restrict__ ei, int E, int n) {
    int e = blockIdx.x * blockDim.x + threadIdx.x;
    if (e < E) {
        int s = ei[e];
        int d = ei[E + e];
        if ((unsigned)d < (unsigned)n && (unsigned)s < (unsigned)n) {
            int p = atomicAdd(&g_cursor[d], 1);
            g_adj[p] = s;
        }
    }
}

// ---------------- tf32 tensor-core GEMM, register-staged double buffer ----------------
__device__ __forceinline__ unsigned f2tf32(float f) {
    unsigned u;
    asm("cvt.rna.tf32.f32 %0, %1;" : "=r"(u) : "f"(f));
    return u;
}

__device__ __forceinline__ void mma_tf32(float* c, const unsigned* a, const unsigned* b) {
    asm volatile(
        "mma.sync.aligned.m16n8k8.row.col.f32.tf32.tf32.f32 "
        "{%0,%1,%2,%3},{%4,%5,%6,%7},{%8,%9},{%0,%1,%2,%3};"
        : "+f"(c[0]), "+f"(c[1]), "+f"(c[2]), "+f"(c[3])
        : "r"(a[0]), "r"(a[1]), "r"(a[2]), "r"(a[3]), "r"(b[0]), "r"(b[1]));
}

__global__ void __launch_bounds__(256) tf32gemm(const float* __restrict__ Aext,
                                                const float* __restrict__ B,
                                                int n, int K, int M, int use_hbuf) {
    const float* A = use_hbuf ? g_hbuf : Aext;
    __shared__ unsigned As[128 * 36];
    __shared__ unsigned Bs[32 * 136];

    const int tid = threadIdx.x;
    const int lane = tid & 31, wid = tid >> 5;
    const int wm = wid & 1, wn = wid >> 1;
    const int m0 = wm * 64, n0 = wn * 32;
    const int row0 = blockIdx.y * 128, col0 = blockIdx.x * 128;

    float acc[4][4][4];
#pragma unroll
    for (int i = 0; i < 4; i++)
#pragma unroll
        for (int j = 0; j < 4; j++)
#pragma unroll
            for (int q = 0; q < 4; q++) acc[i][j][q] = 0.f;

    const int ar = tid >> 3;
    const int ac4 = (tid & 7) * 4;
    const int bk = tid >> 5;
    const int bc4 = (tid & 31) * 4;
    const int colB = col0 + bc4;
    const bool colOk = colB < M;

    float4 pA[4], pB[4];
#pragma unroll
    for (int j = 0; j < 4; j++) {
        int grow = row0 + ar + 32 * j;
        pA[j] = (grow < n) ? *(const float4*)&A[(size_t)grow * K + ac4]
                           : make_float4(0.f, 0.f, 0.f, 0.f);
        pB[j] = colOk ? *(const float4*)&B[(size_t)(bk + 8 * j) * M + colB]
                      : make_float4(0.f, 0.f, 0.f, 0.f);
    }

    for (int k0 = 0; k0 < K; k0 += 32) {
#pragma unroll
        for (int j = 0; j < 4; j++) {
            *(uint4*)&As[(ar + 32 * j) * 36 + ac4] =
                make_uint4(f2tf32(pA[j].x), f2tf32(pA[j].y), f2tf32(pA[j].z), f2tf32(pA[j].w));
            *(uint4*)&Bs[(bk + 8 * j) * 136 + bc4] =
                make_uint4(f2tf32(pB[j].x), f2tf32(pB[j].y), f2tf32(pB[j].z), f2tf32(pB[j].w));
        }
        __syncthreads();

        if (k0 + 32 < K) {
            int kn = k0 + 32;
#pragma unroll
            for (int j = 0; j < 4; j++) {
                int grow = row0 + ar + 32 * j;
                pA[j] = (grow < n) ? *(const float4*)&A[(size_t)grow * K + kn + ac4]
                                   : make_float4(0.f, 0.f, 0.f, 0.f);
                pB[j] = colOk ? *(const float4*)&B[(size_t)(kn + bk + 8 * j) * M + colB]
                              : make_float4(0.f, 0.f, 0.f, 0.f);
            }
        }

#pragma unroll
        for (int k8 = 0; k8 < 32; k8 += 8) {
            unsigned a[4][4], b[4][2];
#pragma unroll
            for (int mt = 0; mt < 4; mt++) {
                int r = m0 + mt * 16 + (lane >> 2);
                int c = k8 + (lane & 3);
                a[mt][0] = As[r * 36 + c];
                a[mt][1] = As[(r + 8) * 36 + c];
                a[mt][2] = As[r * 36 + c + 4];
                a[mt][3] = As[(r + 8) * 36 + c + 4];
            }
#pragma unroll
            for (int nt = 0; nt < 4; nt++) {
                int col = n0 + nt * 8 + (lane >> 2);
                b[nt][0] = Bs[(k8 + (lane & 3)) * 136 + col];
                b[nt][1] = Bs[(k8 + (lane & 3) + 4) * 136 + col];
            }
#pragma unroll
            for (int mt = 0; mt < 4; mt++)
#pragma unroll
                for (int nt = 0; nt < 4; nt++) mma_tf32(acc[mt][nt], a[mt], b[nt]);
        }
        __syncthreads();
    }

#pragma unroll
    for (int mt = 0; mt < 4; mt++) {
#pragma unroll
        for (int nt = 0; nt < 4; nt++) {
            int row = row0 + m0 + mt * 16 + (lane >> 2);
            int col = col0 + n0 + nt * 8 + 2 * (lane & 3);
            if (col < M) {
                if (row < n)
                    *(float2*)&g_gbuf[(size_t)row * M + col] =
                        make_float2(acc[mt][nt][0], acc[mt][nt][1]);
                if (row + 8 < n)
                    *(float2*)&g_gbuf[(size_t)(row + 8) * M + col] =
                        make_float2(acc[mt][nt][2], acc[mt][nt][3]);
            }
        }
    }
}

// ---------------- attention score dots ----------------
template <int H, int C>
__global__ void att_kernel(const float* __restrict__ as, const float* __restrict__ ad, int n) {
    int node = blockIdx.x;
    if (node >= n) return;
    int w = threadIdx.x >> 5, lane = threadIdx.x & 31;
    float vs = 0.f, vd = 0.f;
    const float* row = g_gbuf + (size_t)node * (H * C) + w * C;
#pragma unroll
    for (int c = lane; c < C; c += 32) {
        float x = row[c];
        vs += x * as[w * C + c];
        vd += x * ad[w * C + c];
    }
#pragma unroll
    for (int o = 16; o > 0; o >>= 1) {
        vs += __shfl_down_sync(0xffffffffu, vs, o);
        vd += __shfl_down_sync(0xffffffffu, vd, o);
    }
    if (lane == 0) {
        g_asrc[node * H + w] = vs;
        g_adst[node * H + w] = vd;
    }
}

// ---------------- fused per-head softmax + warp-per-node gather ----------------
// One warp per node. Each lane computes ONLY its own head's weight:
// scalar asrc[s*H+head] load (4 distinct words in one 16B segment per warp),
// 1 leakyrelu + 1 __expf per edge per warp. Denominator accumulated per lane
// (redundant within a head group — reduction-free). No g_w, no atomics.
template <int CH, int H, bool DO_BN>
__global__ void __launch_bounds__(256) agg8_kernel(int n,
                                                   const float* __restrict__ bias,
                                                   const float* __restrict__ bn_g,
                                                   const float* __restrict__ bn_b,
                                                   const float* __restrict__ bn_m,
                                                   const float* __restrict__ bn_v,
                                                   float* __restrict__ out_ext) {
    constexpr int VEC = CH / 32;        // channels per lane (8 or 2)
    constexpr int C = CH / H;

    float* out = out_ext ? out_ext : g_hbuf;
    const int warp = threadIdx.x >> 5;
    const int lane = threadIdx.x & 31;
    const int node = blockIdx.x * 8 + warp;
    if (node >= n) return;
    const int c0 = lane * VEC;
    const int head = c0 / C;

    const int beg = g_rowptr[node];
    const int end = g_rowptr[node + 1];

    const float adst_h = __ldg(&g_adst[node * H + head]);

    float acc[VEC];
#pragma unroll
    for (int v = 0; v < VEC; v++) acc[v] = 0.f;
    float denom = 0.f;

#pragma unroll 4
    for (int i = beg; i < end; i++) {
        const int s = __ldg(&g_adj[i]);                        // warp-broadcast
        float e = __ldg(&g_asrc[s * H + head]) + adst_h;       // 1 segment/warp
        e = (e > 0.f) ? e : 0.2f * e;
        const float w = __expf(e);
        denom += w;
        const float* row = &g_gbuf[(size_t)s * CH + c0];
        if constexpr (VEC == 8) {
            float4 v0 = *(const float4*)row;
            float4 v1 = *(const float4*)(row + 4);
            acc[0] += w * v0.x; acc[1] += w * v0.y;
            acc[2] += w * v0.z; acc[3] += w * v0.w;
            acc[4] += w * v1.x; acc[5] += w * v1.y;
            acc[6] += w * v1.z; acc[7] += w * v1.w;
        } else {
            float2 v0 = *(const float2*)row;
            acc[0] += w * v0.x; acc[1] += w * v0.y;
        }
    }

    const float inv = 1.f / (denom + 1e-16f);
    float o[VEC];
#pragma unroll
    for (int v = 0; v < VEC; v++) o[v] = acc[v] * inv + __ldg(&bias[c0 + v]);
    if (DO_BN) {
#pragma unroll
        for (int v = 0; v < VEC; v++) {
            float val = (o[v] - __ldg(&bn_m[c0 + v])) * rsqrtf(__ldg(&bn_v[c0 + v]) + 1e-5f)
                        * __ldg(&bn_g[c0 + v]) + __ldg(&bn_b[c0 + v]);
            o[v] = (val > 0.f) ? val : expm1f(val);
        }
    }
    if constexpr (VEC == 8) {
        *(float4*)&out[(size_t)node * CH + c0] = make_float4(o[0], o[1], o[2], o[3]);
        *(float4*)&out[(size_t)node * CH + c0 + 4] = make_float4(o[4], o[5], o[6], o[7]);
    } else {
        *(float2*)&out[(size_t)node * CH + c0] = make_float2(o[0], o[1]);
    }
}

// ---------------- launch ----------------
extern "C" void kernel_launch(void* const* d_in, const int* in_sizes, int n_in,
                              void* d_out, int out_size) {
    const float* x   = (const float*)d_in[0];
    const int*   ei  = (const int*)d_in[1];     // int32 (JAX default x64-disabled)
    const float* W0  = (const float*)d_in[2];
    const float* as0 = (const float*)d_in[3];
    const float* ad0 = (const float*)d_in[4];
    const float* b0  = (const float*)d_in[5];
    const float* bn0g = (const float*)d_in[6];
    const float* bn0b = (const float*)d_in[7];
    const float* bn0m = (const float*)d_in[8];
    const float* bn0v = (const float*)d_in[9];
    const float* W1  = (const float*)d_in[10];
    const float* as1 = (const float*)d_in[11];
    const float* ad1 = (const float*)d_in[12];
    const float* b1  = (const float*)d_in[13];
    const float* bn1g = (const float*)d_in[14];
    const float* bn1b = (const float*)d_in[15];
    const float* bn1m = (const float*)d_in[16];
    const float* bn1v = (const float*)d_in[17];
    const float* W2  = (const float*)d_in[18];
    const float* as2 = (const float*)d_in[19];
    const float* ad2 = (const float*)d_in[20];
    const float* b2  = (const float*)d_in[21];

    int n = in_sizes[0] / INC;       // 50000
    int E = in_sizes[1] / 2;         // 800000

    // side stream + events for forked capture (created once, host-side only)
    static cudaStream_t s_side = nullptr;
    static cudaEvent_t s_fork = nullptr, s_join = nullptr;
    if (s_side == nullptr) {
        cudaStreamCreateWithFlags(&s_side, cudaStreamNonBlocking);
        cudaEventCreateWithFlags(&s_fork, cudaEventDisableTiming);
        cudaEventCreateWithFlags(&s_join, cudaEventDisableTiming);
    }

    dim3 gA((HID + 127) / 128, (n + 127) / 128);
    dim3 gC((OUTC + 127) / 128, (n + 127) / 128);
    int gN = (n + 7) / 8;
    int nb = (n + 1023) / 1024;

    // ---- fork: CSR build on side stream, concurrent with layer-0 GEMM+att ----
    cudaEventRecord(s_fork, 0);
    cudaStreamWaitEvent(s_side, s_fork, 0);
    zero_deg_kernel<<<(n + 255) / 256, 256, 0, s_side>>>(n);
    hist_kernel<<<(E + 255) / 256, 256, 0, s_side>>>(ei, E, n);
    scan1_kernel<<<nb, 1024, 0, s_side>>>(n);
    scan2_kernel<<<1, 64, 0, s_side>>>(nb, n);
    scan3_kernel<<<nb, 1024, 0, s_side>>>(n);
    selfloop_kernel<<<(n + 255) / 256, 256, 0, s_side>>>(n);
    scatter_kernel<<<(E + 255) / 256, 256, 0, s_side>>>(ei, E, n);
    cudaEventRecord(s_join, s_side);

    // ---- layer 0 GEMM + att dots (independent of CSR) ----
    tf32gemm<<<gA, 256>>>(x, W0, n, INC, HID, 0);
    att_kernel<NHEADS, HID / NHEADS><<<n, 32 * NHEADS>>>(as0, ad0, n);

    cudaStreamWaitEvent(0, s_join, 0);   // join before first aggregation

    // ---- layer 0: fused softmax+aggregation ----
    agg8_kernel<HID, NHEADS, true><<<gN, 256>>>(n, b0, bn0g, bn0b, bn0m, bn0v, nullptr);

    // ---- layer 1: 256 -> 256, 4 heads, concat, BN+ELU ----
    tf32gemm<<<gA, 256>>>(nullptr, W1, n, HID, HID, 1);
    att_kernel<NHEADS, HID / NHEADS><<<n, 32 * NHEADS>>>(as1, ad1, n);
    agg8_kernel<HID, NHEADS, true><<<gN, 256>>>(n, b1, bn1g, bn1b, bn1m, bn1v, nullptr);

    // ---- layer 2: 256 -> 64, 1 head, mean(=identity), bias only ----
    tf32gemm<<<gC, 256>>>(nullptr, W2, n, HID, OUTC, 1);
    att_kernel<1, OUTC><<<n, 32>>>(as2, ad2, n);
    agg8_kernel<OUTC, 1, false><<<gN, 256>>>(n, b2, b2, b2, b2, b2, (float*)d_out);
}